// round 1
// baseline (speedup 1.0000x reference)
#include <cuda_runtime.h>
#include <cuda_bf16.h>
#include <math.h>

// ---------------- problem constants ----------------
#define T_TOK   2048
#define HID     4096
#define NH      32
#define NKH     8
#define HD      128
#define VDIM    64
#define QKV_N   (NH*HD + NKH*HD + NKH*VDIM)   // 5632
#define K_OFF   (NH*HD)                        // 4096
#define V_OFF   (NH*HD + NKH*HD)               // 5120
#define WINDOW_SZ 1024
#define SCALE_ATTN 0.08838834764831845f        // 128^-0.5
#define V_SCALE_C  1.25f

// ---------------- scratch (no allocs allowed) ----------------
__device__ float g_qkv [T_TOK * QKV_N];        // ~46 MB
__device__ float g_attn[T_TOK * NH * VDIM];    // ~17 MB

// =====================================================================
// SGEMM: C[M,N] = A[M,K] @ B[K,N], all row-major, M%128==0, N%128==0, K%8==0
// 128x128 block, 8x8 per thread, 256 threads.
// =====================================================================
#define BM 128
#define BN 128
#define BK 8
#define TM 8
#define TN 8

__global__ __launch_bounds__(256) void sgemm_kernel(
    const float* __restrict__ A, const float* __restrict__ B,
    float* __restrict__ C, int M, int N, int K)
{
    __shared__ float As[BK][BM];
    __shared__ float Bs[BK][BN];

    const int tid = threadIdx.x;
    const int bx = blockIdx.x;      // N tile
    const int by = blockIdx.y;      // M tile

    const float* Ab = A + (size_t)by * BM * K;
    const float* Bb = B + (size_t)bx * BN;

    const int tRow = tid >> 4;          // 0..15
    const int tCol = tid & 15;          // 0..15

    const int aRow = tid >> 1;          // 0..127
    const int aCol = (tid & 1) * 4;     // 0 or 4
    const int bRow = tid >> 5;          // 0..7
    const int bCol = (tid & 31) * 4;    // 0..124

    float acc[TM][TN];
    #pragma unroll
    for (int i = 0; i < TM; i++)
        #pragma unroll
        for (int j = 0; j < TN; j++) acc[i][j] = 0.f;

    for (int k0 = 0; k0 < K; k0 += BK) {
        float4 av = *(const float4*)(Ab + (size_t)aRow * K + k0 + aCol);
        As[aCol+0][aRow] = av.x;
        As[aCol+1][aRow] = av.y;
        As[aCol+2][aRow] = av.z;
        As[aCol+3][aRow] = av.w;
        float4 bv = *(const float4*)(Bb + (size_t)(k0 + bRow) * N + bCol);
        *(float4*)(&Bs[bRow][bCol]) = bv;
        __syncthreads();

        #pragma unroll
        for (int k = 0; k < BK; k++) {
            float rm[TM], rn[TN];
            #pragma unroll
            for (int i = 0; i < TM; i++) rm[i] = As[k][tRow*TM + i];
            #pragma unroll
            for (int j = 0; j < TN; j++) rn[j] = Bs[k][tCol*TN + j];
            #pragma unroll
            for (int i = 0; i < TM; i++)
                #pragma unroll
                for (int j = 0; j < TN; j++)
                    acc[i][j] = fmaf(rm[i], rn[j], acc[i][j]);
        }
        __syncthreads();
    }

    float* Cb = C + (size_t)by * BM * N + (size_t)bx * BN;
    #pragma unroll
    for (int i = 0; i < TM; i++) {
        #pragma unroll
        for (int j = 0; j < TN; j += 4) {
            float4 v = make_float4(acc[i][j], acc[i][j+1], acc[i][j+2], acc[i][j+3]);
            *(float4*)(Cb + (size_t)(tRow*TM + i) * N + tCol*TN + j) = v;
        }
    }
}

// =====================================================================
// RoPE (q and k heads, pairs (i, i+64)) + V scale, in place on g_qkv.
// One block per token, 256 threads.
// =====================================================================
__global__ __launch_bounds__(256) void rope_kernel(
    float* __restrict__ qkv, const int* __restrict__ positions)
{
    const int t = blockIdx.x;
    const float pos = (float)positions[t];
    float* row = qkv + (size_t)t * QKV_N;
    const int tid = threadIdx.x;

    // 40 rotated heads (32 q + 8 k), 64 pairs each
    for (int idx = tid; idx < 40 * 64; idx += 256) {
        int head = idx >> 6;
        int i = idx & 63;
        float inv = powf(1.0e6f, -(float)i * (1.0f / 64.0f));
        float fr = pos * inv;
        float s, c;
        sincosf(fr, &s, &c);
        int base = (head < NH) ? head * HD : K_OFF + (head - NH) * HD;
        float x1 = row[base + i];
        float x2 = row[base + i + 64];
        row[base + i]      = x1 * c - x2 * s;
        row[base + i + 64] = x2 * c + x1 * s;
    }
    // scale V
    for (int idx = tid; idx < NKH * VDIM; idx += 256) {
        row[V_OFF + idx] *= V_SCALE_C;
    }
}

// =====================================================================
// Flash attention, sliding window 1024, sink logit.
// Block = (head, 64-query tile), 256 threads = 16x16 thread grid,
// each thread owns a 4x4 sub-tile of the 64x64 score/output tiles.
// K stored transposed in smem (KsT[k][c]) so both S and PV inner loops
// use conflict-free LDS.128.
// =====================================================================
#define A_BM 64
#define A_BN 64
#define QS_STRIDE 132         // 128 + 4, keeps float4 alignment
#define KT_STRIDE 68          // 64 + 4
#define ATTN_SMEM ((A_BM*QS_STRIDE + HD*KT_STRIDE + A_BN*KT_STRIDE + A_BM*KT_STRIDE) * 4)

__global__ __launch_bounds__(256) void attn_kernel(
    const float* __restrict__ qkv, const float* __restrict__ sink,
    float* __restrict__ out)
{
    extern __shared__ float sm[];
    float* Qs  = sm;                        // [64][132]  Q rows x dims
    float* KsT = Qs  + A_BM * QS_STRIDE;    // [128][68]  dims x key rows
    float* Vs  = KsT + HD   * KT_STRIDE;    // [64][68]   key rows x vd
    float* Ps  = Vs  + A_BN * KT_STRIDE;    // [64][68]   q rows x key rows

    const int h  = blockIdx.y;
    const int m0 = blockIdx.x * A_BM;
    const int kh = h >> 2;

    const int tid = threadIdx.x;
    const int tx = tid & 15;     // score cols tx*4..+3
    const int ty = tid >> 4;     // score rows ty*4..+3

    const float* Qg = qkv + (size_t)h  * HD;
    const float* Kg = qkv + K_OFF + (size_t)kh * HD;
    const float* Vg = qkv + V_OFF + (size_t)kh * VDIM;

    // load Q tile
    for (int idx = tid; idx < A_BM * HD; idx += 256) {
        int r = idx >> 7, c = idx & 127;
        Qs[r * QS_STRIDE + c] = Qg[(size_t)(m0 + r) * QKV_N + c];
    }

    const float snk = sink[h];
    float m_i[4], l_i[4], O[4][4];
    #pragma unroll
    for (int i = 0; i < 4; i++) {
        m_i[i] = snk;
        l_i[i] = 1.0f;              // accounts for exp(sink - m) term
        #pragma unroll
        for (int j = 0; j < 4; j++) O[i][j] = 0.f;
    }

    int n0_first = m0 - WINDOW_SZ;
    if (n0_first < 0) n0_first = 0;

    for (int n0 = n0_first; n0 <= m0; n0 += A_BN) {
        __syncthreads();   // prev iter done reading KsT/Vs/Ps (and Q load done)

        // load K tile transposed: KsT[k][c]
        for (int idx = tid; idx < A_BN * HD; idx += 256) {
            int r = idx >> 7, k = idx & 127;          // r = key row, k = dim
            KsT[k * KT_STRIDE + r] = Kg[(size_t)(n0 + r) * QKV_N + k];
        }
        // load V tile: Vs[key][vd]
        for (int idx = tid; idx < A_BN * VDIM; idx += 256) {
            int r = idx >> 6, c = idx & 63;
            Vs[r * KT_STRIDE + c] = Vg[(size_t)(n0 + r) * QKV_N + c];
        }
        __syncthreads();

        // ---- S = Q K^T (4x4 per thread), 4 k's at a time ----
        float S[4][4];
        #pragma unroll
        for (int i = 0; i < 4; i++)
            #pragma unroll
            for (int j = 0; j < 4; j++) S[i][j] = 0.f;

        for (int k = 0; k < HD; k += 4) {
            float4 q[4], kk[4];
            #pragma unroll
            for (int i = 0; i < 4; i++)
                q[i] = *(const float4*)&Qs[(ty*4 + i) * QS_STRIDE + k];
            #pragma unroll
            for (int kp = 0; kp < 4; kp++)
                kk[kp] = *(const float4*)&KsT[(k + kp) * KT_STRIDE + tx*4];
            #pragma unroll
            for (int i = 0; i < 4; i++) {
                const float* kv0 = (const float*)&kk[0];
                const float* kv1 = (const float*)&kk[1];
                const float* kv2 = (const float*)&kk[2];
                const float* kv3 = (const float*)&kk[3];
                #pragma unroll
                for (int j = 0; j < 4; j++) {
                    float s = S[i][j];
                    s = fmaf(q[i].x, kv0[j], s);
                    s = fmaf(q[i].y, kv1[j], s);
                    s = fmaf(q[i].z, kv2[j], s);
                    s = fmaf(q[i].w, kv3[j], s);
                    S[i][j] = s;
                }
            }
        }

        // ---- mask + scale ----
        #pragma unroll
        for (int i = 0; i < 4; i++) {
            int gi = m0 + ty*4 + i;
            #pragma unroll
            for (int j = 0; j < 4; j++) {
                int gj = n0 + tx*4 + j;
                bool valid = (gj <= gi) && (gj + WINDOW_SZ > gi);
                S[i][j] = valid ? S[i][j] * SCALE_ATTN : -1.0e30f;
            }
        }

        // ---- online softmax (row reductions across the 16 tx lanes) ----
        #pragma unroll
        for (int i = 0; i < 4; i++) {
            float mx = fmaxf(fmaxf(S[i][0], S[i][1]), fmaxf(S[i][2], S[i][3]));
            #pragma unroll
            for (int d = 8; d > 0; d >>= 1)
                mx = fmaxf(mx, __shfl_xor_sync(0xffffffffu, mx, d));
            float mnew = fmaxf(m_i[i], mx);
            float corr = __expf(m_i[i] - mnew);
            m_i[i] = mnew;
            l_i[i] *= corr;
            #pragma unroll
            for (int j = 0; j < 4; j++) O[i][j] *= corr;
            float ps = 0.f;
            #pragma unroll
            for (int j = 0; j < 4; j++) {
                float p = __expf(S[i][j] - mnew);
                S[i][j] = p;
                ps += p;
            }
            #pragma unroll
            for (int d = 8; d > 0; d >>= 1)
                ps += __shfl_xor_sync(0xffffffffu, ps, d);
            l_i[i] += ps;
        }

        // ---- store P ----
        #pragma unroll
        for (int i = 0; i < 4; i++)
            #pragma unroll
            for (int j = 0; j < 4; j++)
                Ps[(ty*4 + i) * KT_STRIDE + tx*4 + j] = S[i][j];
        __syncthreads();

        // ---- O += P @ V ----
        for (int k = 0; k < A_BN; k += 4) {
            float4 p[4], v[4];
            #pragma unroll
            for (int i = 0; i < 4; i++)
                p[i] = *(const float4*)&Ps[(ty*4 + i) * KT_STRIDE + k];
            #pragma unroll
            for (int kp = 0; kp < 4; kp++)
                v[kp] = *(const float4*)&Vs[(k + kp) * KT_STRIDE + tx*4];
            #pragma unroll
            for (int i = 0; i < 4; i++) {
                const float* v0 = (const float*)&v[0];
                const float* v1 = (const float*)&v[1];
                const float* v2 = (const float*)&v[2];
                const float* v3 = (const float*)&v[3];
                #pragma unroll
                for (int j = 0; j < 4; j++) {
                    float o = O[i][j];
                    o = fmaf(p[i].x, v0[j], o);
                    o = fmaf(p[i].y, v1[j], o);
                    o = fmaf(p[i].z, v2[j], o);
                    o = fmaf(p[i].w, v3[j], o);
                    O[i][j] = o;
                }
            }
        }
    }

    // epilogue: out[t, h*64 + vd] = O / l
    #pragma unroll
    for (int i = 0; i < 4; i++) {
        float inv_l = 1.0f / l_i[i];
        int gi = m0 + ty*4 + i;
        #pragma unroll
        for (int j = 0; j < 4; j++) {
            out[(size_t)gi * (NH * VDIM) + h * VDIM + tx*4 + j] = O[i][j] * inv_l;
        }
    }
}

// =====================================================================
// launch
// =====================================================================
extern "C" void kernel_launch(void* const* d_in, const int* in_sizes, int n_in,
                              void* d_out, int out_size)
{
    const int*   positions = (const int*)  d_in[0];
    const float* hidden    = (const float*)d_in[1];
    const float* Wqkv      = (const float*)d_in[2];
    const float* Wo        = (const float*)d_in[3];
    const float* sink      = (const float*)d_in[4];
    float* out = (float*)d_out;

    float *qkv, *attn;
    cudaGetSymbolAddress((void**)&qkv,  g_qkv);
    cudaGetSymbolAddress((void**)&attn, g_attn);

    cudaFuncSetAttribute(attn_kernel,
                         cudaFuncAttributeMaxDynamicSharedMemorySize, ATTN_SMEM);

    // 1) QKV projection
    {
        dim3 grid(QKV_N / BN, T_TOK / BM);
        sgemm_kernel<<<grid, 256>>>(hidden, Wqkv, qkv, T_TOK, QKV_N, HID);
    }
    // 2) RoPE + V scale (in place)
    rope_kernel<<<T_TOK, 256>>>(qkv, positions);
    // 3) attention
    {
        dim3 grid(T_TOK / A_BM, NH);
        attn_kernel<<<grid, 256, ATTN_SMEM>>>(qkv, sink, attn);
    }
    // 4) output projection
    {
        dim3 grid(HID / BN, T_TOK / BM);
        sgemm_kernel<<<grid, 256>>>(attn, Wo, out, T_TOK, HID, NH * VDIM);
    }
}

// round 4
// speedup vs baseline: 2.5095x; 2.5095x over previous
#include <cuda_runtime.h>
#include <cuda_bf16.h>
#include <cstdint>
#include <math.h>

typedef unsigned int u32;

// ---------------- problem constants ----------------
#define T_TOK   2048
#define HID     4096
#define NH      32
#define NKH     8
#define HD      128
#define VDIM    64
#define QKV_N   (NH*HD + NKH*HD + NKH*VDIM)   // 5632
#define K_OFF   (NH*HD)                        // 4096
#define V_OFF   (NH*HD + NKH*HD)               // 5120
#define WINDOW_SZ 1024
#define SCALE_ATTN 0.08838834764831845f        // 128^-0.5
#define V_SCALE_C  1.25f

// ---------------- scratch (no allocs allowed) ----------------
__device__ float g_qkv [T_TOK * QKV_N];        // ~46 MB
__device__ float g_attn[T_TOK * NH * VDIM];    // ~17 MB

// =====================================================================
// TF32 tensor-core GEMM: C[M,N] = A[M,K] @ B[K,N], row-major.
// 128x128 block tile, BK=32, 8 warps in 2x4 grid, warp tile 64x32,
// mma.sync.m16n8k8 tf32. Double-buffered smem.
// =====================================================================
#define GBM 128
#define GBN 128
#define GBK 32
#define AS_STRIDE 36      // (4g+tg)%32 all-distinct  -> conflict-free A frags
#define BS_STRIDE 132     // (4tg+g)%32 all-distinct  -> conflict-free B frags
#define AS_ELEMS (GBM*AS_STRIDE)
#define BS_ELEMS (GBK*BS_STRIDE)
#define GEMM_SMEM ((2*AS_ELEMS + 2*BS_ELEMS) * 4)

__device__ __forceinline__ u32 f2tf32(float f) {
    u32 r;
    asm("cvt.rna.tf32.f32 %0, %1;" : "=r"(r) : "f"(f));
    return r;
}

__device__ __forceinline__ void mma_tf32(float c[4], const u32 a[4],
                                         const u32 b[2]) {
    asm volatile(
        "mma.sync.aligned.m16n8k8.row.col.f32.tf32.tf32.f32 "
        "{%0,%1,%2,%3}, {%4,%5,%6,%7}, {%8,%9}, {%0,%1,%2,%3};\n"
        : "+f"(c[0]), "+f"(c[1]), "+f"(c[2]), "+f"(c[3])
        : "r"(a[0]), "r"(a[1]), "r"(a[2]), "r"(a[3]), "r"(b[0]), "r"(b[1]));
}

__global__ __launch_bounds__(256, 2) void gemm_tf32_kernel(
    const float* __restrict__ A, const float* __restrict__ B,
    float* __restrict__ C, int M, int N, int K)
{
    extern __shared__ u32 smem_u[];
    u32* As = smem_u;                    // [2][128][36]
    u32* Bs = smem_u + 2 * AS_ELEMS;     // [2][32][132]

    const int tid  = threadIdx.x;
    const int warp = tid >> 5;
    const int lane = tid & 31;
    const int wr = warp >> 2;        // 0..1  warp row
    const int wc = warp & 3;         // 0..3  warp col
    const int g  = lane >> 2;        // 0..7
    const int tg = lane & 3;         // 0..3

    const int bx = blockIdx.x, by = blockIdx.y;
    const float* Ab = A + (size_t)by * GBM * K;
    const float* Bb = B + (size_t)bx * GBN;

    // global->smem mapping
    const int arow0 = tid >> 3;            // 0..31 (4 passes of +32)
    const int acol  = (tid & 7) * 4;
    const int brow0 = tid >> 5;            // 0..7  (4 passes of +8)
    const int bcol  = (tid & 31) * 4;

    float acc[4][4][4];
    #pragma unroll
    for (int i = 0; i < 4; i++)
        #pragma unroll
        for (int j = 0; j < 4; j++)
            #pragma unroll
            for (int r = 0; r < 4; r++) acc[i][j][r] = 0.f;

    const int nc = K / GBK;

    // ---- prologue: chunk 0 straight to smem buf 0 ----
    #pragma unroll
    for (int p = 0; p < 4; p++) {
        int r = arow0 + p * 32;
        float4 v = *(const float4*)(Ab + (size_t)r * K + acol);
        u32* d = &As[r * AS_STRIDE + acol];
        d[0] = f2tf32(v.x); d[1] = f2tf32(v.y); d[2] = f2tf32(v.z); d[3] = f2tf32(v.w);
    }
    #pragma unroll
    for (int p = 0; p < 4; p++) {
        int r = brow0 + p * 8;
        float4 v = *(const float4*)(Bb + (size_t)r * N + bcol);
        u32* d = &Bs[r * BS_STRIDE + bcol];
        d[0] = f2tf32(v.x); d[1] = f2tf32(v.y); d[2] = f2tf32(v.z); d[3] = f2tf32(v.w);
    }
    __syncthreads();

    int pb = 0;
    for (int c = 0; c < nc; c++) {
        float4 stA[4], stB[4];
        const bool has_next = (c + 1 < nc);
        if (has_next) {
            int k0 = (c + 1) * GBK;
            #pragma unroll
            for (int p = 0; p < 4; p++)
                stA[p] = *(const float4*)(Ab + (size_t)(arow0 + p*32) * K + k0 + acol);
            #pragma unroll
            for (int p = 0; p < 4; p++)
                stB[p] = *(const float4*)(Bb + (size_t)(k0 + brow0 + p*8) * N + bcol);
        }

        const u32* Ac = As + pb * AS_ELEMS;
        const u32* Bc = Bs + pb * BS_ELEMS;

        #pragma unroll
        for (int ks = 0; ks < 4; ks++) {
            u32 af[4][4], bf[4][2];
            #pragma unroll
            for (int mt = 0; mt < 4; mt++) {
                int base = (wr*64 + mt*16 + g) * AS_STRIDE + ks*8 + tg;
                af[mt][0] = Ac[base];
                af[mt][1] = Ac[base + 8*AS_STRIDE];
                af[mt][2] = Ac[base + 4];
                af[mt][3] = Ac[base + 8*AS_STRIDE + 4];
            }
            #pragma unroll
            for (int nt = 0; nt < 4; nt++) {
                int col = wc*32 + nt*8 + g;
                int idx = (ks*8 + tg) * BS_STRIDE + col;
                bf[nt][0] = Bc[idx];
                bf[nt][1] = Bc[idx + 4*BS_STRIDE];
            }
            #pragma unroll
            for (int mt = 0; mt < 4; mt++)
                #pragma unroll
                for (int nt = 0; nt < 4; nt++)
                    mma_tf32(acc[mt][nt], af[mt], bf[nt]);
        }

        if (has_next) {
            u32* An = As + (1 - pb) * AS_ELEMS;
            u32* Bn = Bs + (1 - pb) * BS_ELEMS;
            #pragma unroll
            for (int p = 0; p < 4; p++) {
                u32* d = &An[(arow0 + p*32) * AS_STRIDE + acol];
                d[0]=f2tf32(stA[p].x); d[1]=f2tf32(stA[p].y);
                d[2]=f2tf32(stA[p].z); d[3]=f2tf32(stA[p].w);
            }
            #pragma unroll
            for (int p = 0; p < 4; p++) {
                u32* d = &Bn[(brow0 + p*8) * BS_STRIDE + bcol];
                d[0]=f2tf32(stB[p].x); d[1]=f2tf32(stB[p].y);
                d[2]=f2tf32(stB[p].z); d[3]=f2tf32(stB[p].w);
            }
            __syncthreads();
            pb ^= 1;
        }
    }

    // ---- epilogue ----
    float* Cb = C + (size_t)by * GBM * N + (size_t)bx * GBN;
    #pragma unroll
    for (int mt = 0; mt < 4; mt++) {
        int row = wr*64 + mt*16 + g;
        #pragma unroll
        for (int nt = 0; nt < 4; nt++) {
            int col = wc*32 + nt*8 + tg*2;
            *(float2*)(Cb + (size_t)row * N + col) =
                make_float2(acc[mt][nt][0], acc[mt][nt][1]);
            *(float2*)(Cb + (size_t)(row + 8) * N + col) =
                make_float2(acc[mt][nt][2], acc[mt][nt][3]);
        }
    }
}

// =====================================================================
// RoPE (q and k heads, pairs (i, i+64)) + V scale, in place on g_qkv.
// =====================================================================
__global__ __launch_bounds__(256) void rope_kernel(
    float* __restrict__ qkv, const int* __restrict__ positions)
{
    const int t = blockIdx.x;
    const float pos = (float)positions[t];
    float* row = qkv + (size_t)t * QKV_N;
    const int tid = threadIdx.x;

    for (int idx = tid; idx < 40 * 64; idx += 256) {
        int head = idx >> 6;
        int i = idx & 63;
        float inv = powf(1.0e6f, -(float)i * (1.0f / 64.0f));
        float fr = pos * inv;
        float s, c;
        sincosf(fr, &s, &c);
        int base = (head < NH) ? head * HD : K_OFF + (head - NH) * HD;
        float x1 = row[base + i];
        float x2 = row[base + i + 64];
        row[base + i]      = x1 * c - x2 * s;
        row[base + i + 64] = x2 * c + x1 * s;
    }
    for (int idx = tid; idx < NKH * VDIM; idx += 256) {
        row[V_OFF + idx] *= V_SCALE_C;
    }
}

// =====================================================================
// Flash attention, sliding window 1024, sink logit (fp32 FFMA).
// =====================================================================
#define A_BM 64
#define A_BN 64
#define QS_STRIDE 132
#define KT_STRIDE 68
#define ATTN_SMEM ((A_BM*QS_STRIDE + HD*KT_STRIDE + A_BN*KT_STRIDE + A_BM*KT_STRIDE) * 4)

__global__ __launch_bounds__(256) void attn_kernel(
    const float* __restrict__ qkv, const float* __restrict__ sink,
    float* __restrict__ out)
{
    extern __shared__ float sm[];
    float* Qs  = sm;
    float* KsT = Qs  + A_BM * QS_STRIDE;
    float* Vs  = KsT + HD   * KT_STRIDE;
    float* Ps  = Vs  + A_BN * KT_STRIDE;

    const int h  = blockIdx.y;
    const int m0 = blockIdx.x * A_BM;
    const int kh = h >> 2;

    const int tid = threadIdx.x;
    const int tx = tid & 15;
    const int ty = tid >> 4;

    const float* Qg = qkv + (size_t)h  * HD;
    const float* Kg = qkv + K_OFF + (size_t)kh * HD;
    const float* Vg = qkv + V_OFF + (size_t)kh * VDIM;

    for (int idx = tid; idx < A_BM * HD; idx += 256) {
        int r = idx >> 7, c = idx & 127;
        Qs[r * QS_STRIDE + c] = Qg[(size_t)(m0 + r) * QKV_N + c];
    }

    const float snk = sink[h];
    float m_i[4], l_i[4], O[4][4];
    #pragma unroll
    for (int i = 0; i < 4; i++) {
        m_i[i] = snk;
        l_i[i] = 1.0f;
        #pragma unroll
        for (int j = 0; j < 4; j++) O[i][j] = 0.f;
    }

    int n0_first = m0 - WINDOW_SZ;
    if (n0_first < 0) n0_first = 0;

    for (int n0 = n0_first; n0 <= m0; n0 += A_BN) {
        __syncthreads();

        for (int idx = tid; idx < A_BN * HD; idx += 256) {
            int r = idx >> 7, k = idx & 127;
            KsT[k * KT_STRIDE + r] = Kg[(size_t)(n0 + r) * QKV_N + k];
        }
        for (int idx = tid; idx < A_BN * VDIM; idx += 256) {
            int r = idx >> 6, c = idx & 63;
            Vs[r * KT_STRIDE + c] = Vg[(size_t)(n0 + r) * QKV_N + c];
        }
        __syncthreads();

        float S[4][4];
        #pragma unroll
        for (int i = 0; i < 4; i++)
            #pragma unroll
            for (int j = 0; j < 4; j++) S[i][j] = 0.f;

        for (int k = 0; k < HD; k += 4) {
            float4 q[4], kk[4];
            #pragma unroll
            for (int i = 0; i < 4; i++)
                q[i] = *(const float4*)&Qs[(ty*4 + i) * QS_STRIDE + k];
            #pragma unroll
            for (int kp = 0; kp < 4; kp++)
                kk[kp] = *(const float4*)&KsT[(k + kp) * KT_STRIDE + tx*4];
            #pragma unroll
            for (int i = 0; i < 4; i++) {
                const float* kv0 = (const float*)&kk[0];
                const float* kv1 = (const float*)&kk[1];
                const float* kv2 = (const float*)&kk[2];
                const float* kv3 = (const float*)&kk[3];
                #pragma unroll
                for (int j = 0; j < 4; j++) {
                    float s = S[i][j];
                    s = fmaf(q[i].x, kv0[j], s);
                    s = fmaf(q[i].y, kv1[j], s);
                    s = fmaf(q[i].z, kv2[j], s);
                    s = fmaf(q[i].w, kv3[j], s);
                    S[i][j] = s;
                }
            }
        }

        #pragma unroll
        for (int i = 0; i < 4; i++) {
            int gi = m0 + ty*4 + i;
            #pragma unroll
            for (int j = 0; j < 4; j++) {
                int gj = n0 + tx*4 + j;
                bool valid = (gj <= gi) && (gj + WINDOW_SZ > gi);
                S[i][j] = valid ? S[i][j] * SCALE_ATTN : -1.0e30f;
            }
        }

        #pragma unroll
        for (int i = 0; i < 4; i++) {
            float mx = fmaxf(fmaxf(S[i][0], S[i][1]), fmaxf(S[i][2], S[i][3]));
            #pragma unroll
            for (int d = 8; d > 0; d >>= 1)
                mx = fmaxf(mx, __shfl_xor_sync(0xffffffffu, mx, d));
            float mnew = fmaxf(m_i[i], mx);
            float corr = __expf(m_i[i] - mnew);
            m_i[i] = mnew;
            l_i[i] *= corr;
            #pragma unroll
            for (int j = 0; j < 4; j++) O[i][j] *= corr;
            float ps = 0.f;
            #pragma unroll
            for (int j = 0; j < 4; j++) {
                float p = __expf(S[i][j] - mnew);
                S[i][j] = p;
                ps += p;
            }
            #pragma unroll
            for (int d = 8; d > 0; d >>= 1)
                ps += __shfl_xor_sync(0xffffffffu, ps, d);
            l_i[i] += ps;
        }

        #pragma unroll
        for (int i = 0; i < 4; i++)
            #pragma unroll
            for (int j = 0; j < 4; j++)
                Ps[(ty*4 + i) * KT_STRIDE + tx*4 + j] = S[i][j];
        __syncthreads();

        for (int k = 0; k < A_BN; k += 4) {
            float4 p[4], v[4];
            #pragma unroll
            for (int i = 0; i < 4; i++)
                p[i] = *(const float4*)&Ps[(ty*4 + i) * KT_STRIDE + k];
            #pragma unroll
            for (int kp = 0; kp < 4; kp++)
                v[kp] = *(const float4*)&Vs[(k + kp) * KT_STRIDE + tx*4];
            #pragma unroll
            for (int i = 0; i < 4; i++) {
                const float* v0 = (const float*)&v[0];
                const float* v1 = (const float*)&v[1];
                const float* v2 = (const float*)&v[2];
                const float* v3 = (const float*)&v[3];
                #pragma unroll
                for (int j = 0; j < 4; j++) {
                    float o = O[i][j];
                    o = fmaf(p[i].x, v0[j], o);
                    o = fmaf(p[i].y, v1[j], o);
                    o = fmaf(p[i].z, v2[j], o);
                    o = fmaf(p[i].w, v3[j], o);
                    O[i][j] = o;
                }
            }
        }
    }

    #pragma unroll
    for (int i = 0; i < 4; i++) {
        float inv_l = 1.0f / l_i[i];
        int gi = m0 + ty*4 + i;
        #pragma unroll
        for (int j = 0; j < 4; j++) {
            out[(size_t)gi * (NH * VDIM) + h * VDIM + tx*4 + j] = O[i][j] * inv_l;
        }
    }
}

// =====================================================================
// launch
// =====================================================================
extern "C" void kernel_launch(void* const* d_in, const int* in_sizes, int n_in,
                              void* d_out, int out_size)
{
    const int*   positions = (const int*)  d_in[0];
    const float* hidden    = (const float*)d_in[1];
    const float* Wqkv      = (const float*)d_in[2];
    const float* Wo        = (const float*)d_in[3];
    const float* sink      = (const float*)d_in[4];
    float* out = (float*)d_out;

    float *qkv, *attn;
    cudaGetSymbolAddress((void**)&qkv,  g_qkv);
    cudaGetSymbolAddress((void**)&attn, g_attn);

    cudaFuncSetAttribute(gemm_tf32_kernel,
                         cudaFuncAttributeMaxDynamicSharedMemorySize, GEMM_SMEM);
    cudaFuncSetAttribute(attn_kernel,
                         cudaFuncAttributeMaxDynamicSharedMemorySize, ATTN_SMEM);

    // 1) QKV projection (tf32 tensor cores)
    {
        dim3 grid(QKV_N / GBN, T_TOK / GBM);
        gemm_tf32_kernel<<<grid, 256, GEMM_SMEM>>>(hidden, Wqkv, qkv,
                                                   T_TOK, QKV_N, HID);
    }
    // 2) RoPE + V scale (in place)
    rope_kernel<<<T_TOK, 256>>>(qkv, positions);
    // 3) attention
    {
        dim3 grid(T_TOK / A_BM, NH);
        attn_kernel<<<grid, 256, ATTN_SMEM>>>(qkv, sink, attn);
    }
    // 4) output projection (tf32 tensor cores)
    {
        dim3 grid(HID / GBN, T_TOK / GBM);
        gemm_tf32_kernel<<<grid, 256, GEMM_SMEM>>>(attn, Wo, out,
                                                   T_TOK, HID, NH * VDIM);
    }
}

// round 5
// speedup vs baseline: 2.8732x; 1.1449x over previous
#include <cuda_runtime.h>
#include <cuda_bf16.h>
#include <cstdint>
#include <math.h>

typedef unsigned int u32;

// ---------------- problem constants ----------------
#define T_TOK   2048
#define HID     4096
#define NH      32
#define NKH     8
#define HD      128
#define VDIM    64
#define QKV_N   (NH*HD + NKH*HD + NKH*VDIM)   // 5632
#define K_OFF   (NH*HD)                        // 4096
#define V_OFF   (NH*HD + NKH*HD)               // 5120
#define WINDOW_SZ 1024
#define SCALE_ATTN 0.08838834764831845f        // 128^-0.5
#define V_SCALE_C  1.25f

// ---------------- scratch (no allocs allowed) ----------------
__device__ float g_qkv [T_TOK * QKV_N];
__device__ float g_attn[T_TOK * NH * VDIM];

// =====================================================================
// common mma helpers
// =====================================================================
__device__ __forceinline__ u32 f2tf32(float f) {
    u32 r;
    asm("cvt.rna.tf32.f32 %0, %1;" : "=r"(r) : "f"(f));
    return r;
}

__device__ __forceinline__ void mma_tf32(float c[4], const u32 a[4],
                                         const u32 b[2]) {
    asm volatile(
        "mma.sync.aligned.m16n8k8.row.col.f32.tf32.tf32.f32 "
        "{%0,%1,%2,%3}, {%4,%5,%6,%7}, {%8,%9}, {%0,%1,%2,%3};\n"
        : "+f"(c[0]), "+f"(c[1]), "+f"(c[2]), "+f"(c[3])
        : "r"(a[0]), "r"(a[1]), "r"(a[2]), "r"(a[3]), "r"(b[0]), "r"(b[1]));
}

// =====================================================================
// TF32 tensor-core GEMM (unchanged from passing round):
// C[M,N] = A[M,K] @ B[K,N], 128x128 tile, BK=32, 8 warps, m16n8k8.
// =====================================================================
#define GBM 128
#define GBN 128
#define GBK 32
#define AS_STRIDE 36
#define BS_STRIDE 132
#define AS_ELEMS (GBM*AS_STRIDE)
#define BS_ELEMS (GBK*BS_STRIDE)
#define GEMM_SMEM ((2*AS_ELEMS + 2*BS_ELEMS) * 4)

__global__ __launch_bounds__(256, 2) void gemm_tf32_kernel(
    const float* __restrict__ A, const float* __restrict__ B,
    float* __restrict__ C, int M, int N, int K)
{
    extern __shared__ u32 smem_u[];
    u32* As = smem_u;
    u32* Bs = smem_u + 2 * AS_ELEMS;

    const int tid  = threadIdx.x;
    const int warp = tid >> 5;
    const int lane = tid & 31;
    const int wr = warp >> 2;
    const int wc = warp & 3;
    const int g  = lane >> 2;
    const int tg = lane & 3;

    const int bx = blockIdx.x, by = blockIdx.y;
    const float* Ab = A + (size_t)by * GBM * K;
    const float* Bb = B + (size_t)bx * GBN;

    const int arow0 = tid >> 3;
    const int acol  = (tid & 7) * 4;
    const int brow0 = tid >> 5;
    const int bcol  = (tid & 31) * 4;

    float acc[4][4][4];
    #pragma unroll
    for (int i = 0; i < 4; i++)
        #pragma unroll
        for (int j = 0; j < 4; j++)
            #pragma unroll
            for (int r = 0; r < 4; r++) acc[i][j][r] = 0.f;

    const int nc = K / GBK;

    #pragma unroll
    for (int p = 0; p < 4; p++) {
        int r = arow0 + p * 32;
        float4 v = *(const float4*)(Ab + (size_t)r * K + acol);
        u32* d = &As[r * AS_STRIDE + acol];
        d[0] = f2tf32(v.x); d[1] = f2tf32(v.y); d[2] = f2tf32(v.z); d[3] = f2tf32(v.w);
    }
    #pragma unroll
    for (int p = 0; p < 4; p++) {
        int r = brow0 + p * 8;
        float4 v = *(const float4*)(Bb + (size_t)r * N + bcol);
        u32* d = &Bs[r * BS_STRIDE + bcol];
        d[0] = f2tf32(v.x); d[1] = f2tf32(v.y); d[2] = f2tf32(v.z); d[3] = f2tf32(v.w);
    }
    __syncthreads();

    int pb = 0;
    for (int c = 0; c < nc; c++) {
        float4 stA[4], stB[4];
        const bool has_next = (c + 1 < nc);
        if (has_next) {
            int k0 = (c + 1) * GBK;
            #pragma unroll
            for (int p = 0; p < 4; p++)
                stA[p] = *(const float4*)(Ab + (size_t)(arow0 + p*32) * K + k0 + acol);
            #pragma unroll
            for (int p = 0; p < 4; p++)
                stB[p] = *(const float4*)(Bb + (size_t)(k0 + brow0 + p*8) * N + bcol);
        }

        const u32* Ac = As + pb * AS_ELEMS;
        const u32* Bc = Bs + pb * BS_ELEMS;

        #pragma unroll
        for (int ks = 0; ks < 4; ks++) {
            u32 af[4][4], bf[4][2];
            #pragma unroll
            for (int mt = 0; mt < 4; mt++) {
                int base = (wr*64 + mt*16 + g) * AS_STRIDE + ks*8 + tg;
                af[mt][0] = Ac[base];
                af[mt][1] = Ac[base + 8*AS_STRIDE];
                af[mt][2] = Ac[base + 4];
                af[mt][3] = Ac[base + 8*AS_STRIDE + 4];
            }
            #pragma unroll
            for (int nt = 0; nt < 4; nt++) {
                int col = wc*32 + nt*8 + g;
                int idx = (ks*8 + tg) * BS_STRIDE + col;
                bf[nt][0] = Bc[idx];
                bf[nt][1] = Bc[idx + 4*BS_STRIDE];
            }
            #pragma unroll
            for (int mt = 0; mt < 4; mt++)
                #pragma unroll
                for (int nt = 0; nt < 4; nt++)
                    mma_tf32(acc[mt][nt], af[mt], bf[nt]);
        }

        if (has_next) {
            u32* An = As + (1 - pb) * AS_ELEMS;
            u32* Bn = Bs + (1 - pb) * BS_ELEMS;
            #pragma unroll
            for (int p = 0; p < 4; p++) {
                u32* d = &An[(arow0 + p*32) * AS_STRIDE + acol];
                d[0]=f2tf32(stA[p].x); d[1]=f2tf32(stA[p].y);
                d[2]=f2tf32(stA[p].z); d[3]=f2tf32(stA[p].w);
            }
            #pragma unroll
            for (int p = 0; p < 4; p++) {
                u32* d = &Bn[(brow0 + p*8) * BS_STRIDE + bcol];
                d[0]=f2tf32(stB[p].x); d[1]=f2tf32(stB[p].y);
                d[2]=f2tf32(stB[p].z); d[3]=f2tf32(stB[p].w);
            }
            __syncthreads();
            pb ^= 1;
        }
    }

    float* Cb = C + (size_t)by * GBM * N + (size_t)bx * GBN;
    #pragma unroll
    for (int mt = 0; mt < 4; mt++) {
        int row = wr*64 + mt*16 + g;
        #pragma unroll
        for (int nt = 0; nt < 4; nt++) {
            int col = wc*32 + nt*8 + tg*2;
            *(float2*)(Cb + (size_t)row * N + col) =
                make_float2(acc[mt][nt][0], acc[mt][nt][1]);
            *(float2*)(Cb + (size_t)(row + 8) * N + col) =
                make_float2(acc[mt][nt][2], acc[mt][nt][3]);
        }
    }
}

// =====================================================================
// RoPE + V scale. sincos computed ONCE per (token, i) into smem, then
// applied to all 40 rotated heads.
// =====================================================================
__global__ __launch_bounds__(256) void rope_kernel(
    float* __restrict__ qkv, const int* __restrict__ positions)
{
    __shared__ float cs[64], sn[64];
    const int t = blockIdx.x;
    const int tid = threadIdx.x;
    float* row = qkv + (size_t)t * QKV_N;

    if (tid < 64) {
        float pos = (float)positions[t];
        float inv = powf(1.0e6f, -(float)tid * (1.0f / 64.0f));
        float fr = pos * inv;
        float s, c;
        sincosf(fr, &s, &c);
        cs[tid] = c; sn[tid] = s;
    }
    __syncthreads();

    for (int idx = tid; idx < 40 * 64; idx += 256) {
        int head = idx >> 6;
        int i = idx & 63;
        int base = (head < NH) ? head * HD : K_OFF + (head - NH) * HD;
        float c = cs[i], s = sn[i];
        float x1 = row[base + i];
        float x2 = row[base + i + 64];
        row[base + i]      = x1 * c - x2 * s;
        row[base + i + 64] = x2 * c + x1 * s;
    }
    for (int idx = tid; idx < NKH * VDIM; idx += 256) {
        row[V_OFF + idx] *= V_SCALE_C;
    }
}

// =====================================================================
// Tensor-core flash attention (tf32 mma), sliding window 1024, sink.
// Block = (head, 64 q rows), 4 warps, each warp owns 16 q rows (m16).
// S = Q K^T via 3-pass split-tf32 (near-fp32). P*V via plain tf32.
// =====================================================================
#define A_BM 64
#define QK_STRIDE 132          // (4g+tg) distinct banks for frag loads
#define V_STRIDE  68
#define ATTN_SMEM ((2*64*QK_STRIDE + 2*64*V_STRIDE) * 4)   // 100 KB

__global__ __launch_bounds__(128) void attn_kernel(
    const float* __restrict__ qkv, const float* __restrict__ sink,
    float* __restrict__ out)
{
    extern __shared__ float sm[];
    float* Qs = sm;                              // [64][132] fp32
    float* Ks = Qs + 64 * QK_STRIDE;             // [64][132] fp32
    float* Vs = Ks + 64 * QK_STRIDE;             // [64][68]  tf32-rounded
    float* Pw = Vs + 64 * V_STRIDE;              // [4][16][68] warp-private P

    const int h  = blockIdx.y;
    const int m0 = blockIdx.x * A_BM;
    const int kh = h >> 2;

    const int tid  = threadIdx.x;
    const int warp = tid >> 5;
    const int lane = tid & 31;
    const int g  = lane >> 2;       // 0..7  (quad id = frag row group)
    const int tg = lane & 3;        // 0..3
    const int wm = warp * 16;       // warp's q-row offset in tile
    float* Ps = Pw + warp * 16 * V_STRIDE;

    const float* Qg = qkv + (size_t)m0 * QKV_N + h * HD;
    const float* Kg = qkv + K_OFF + (size_t)kh * HD;
    const float* Vg = qkv + V_OFF + (size_t)kh * VDIM;

    // ---- load Q tile (fp32, split on the fly later) ----
    for (int idx = tid; idx < 64 * 32; idx += 128) {
        int r = idx >> 5, c4 = (idx & 31) * 4;
        *(float4*)&Qs[r * QK_STRIDE + c4] =
            *(const float4*)(Qg + (size_t)r * QKV_N + c4);
    }

    const float snk = sink[h];
    float m_r[2] = {snk, snk};
    float l_r[2] = {1.0f, 1.0f};
    float O[8][4];
    #pragma unroll
    for (int nt = 0; nt < 8; nt++)
        #pragma unroll
        for (int r = 0; r < 4; r++) O[nt][r] = 0.f;

    const int gi0 = m0 + wm + g;
    const int gi1 = gi0 + 8;

    int n0s = m0 - WINDOW_SZ;
    if (n0s < 0) n0s = 0;

    for (int n0 = n0s; n0 <= m0; n0 += 64) {
        __syncthreads();   // previous K/V fully consumed (and Q load done)

        // ---- load K tile (fp32) ----
        for (int idx = tid; idx < 64 * 32; idx += 128) {
            int r = idx >> 5, c4 = (idx & 31) * 4;
            *(float4*)&Ks[r * QK_STRIDE + c4] =
                *(const float4*)(Kg + (size_t)(n0 + r) * QKV_N + c4);
        }
        // ---- load V tile (pre-rounded to tf32) ----
        for (int idx = tid; idx < 64 * 16; idx += 128) {
            int r = idx >> 4, c4 = (idx & 15) * 4;
            float4 v = *(const float4*)(Vg + (size_t)(n0 + r) * QKV_N + c4);
            float* d = &Vs[r * V_STRIDE + c4];
            d[0] = __uint_as_float(f2tf32(v.x));
            d[1] = __uint_as_float(f2tf32(v.y));
            d[2] = __uint_as_float(f2tf32(v.z));
            d[3] = __uint_as_float(f2tf32(v.w));
        }
        __syncthreads();

        // ---- S = Q K^T, 3-pass split tf32 ----
        float Sa[8][4];
        #pragma unroll
        for (int nt = 0; nt < 8; nt++)
            #pragma unroll
            for (int r = 0; r < 4; r++) Sa[nt][r] = 0.f;

        #pragma unroll
        for (int ks = 0; ks < 16; ks++) {
            int k0 = ks * 8;
            float a0 = Qs[(wm + g)     * QK_STRIDE + k0 + tg];
            float a1 = Qs[(wm + g + 8) * QK_STRIDE + k0 + tg];
            float a2 = Qs[(wm + g)     * QK_STRIDE + k0 + tg + 4];
            float a3 = Qs[(wm + g + 8) * QK_STRIDE + k0 + tg + 4];
            u32 ahi[4], alo[4];
            ahi[0] = f2tf32(a0); alo[0] = f2tf32(a0 - __uint_as_float(ahi[0]));
            ahi[1] = f2tf32(a1); alo[1] = f2tf32(a1 - __uint_as_float(ahi[1]));
            ahi[2] = f2tf32(a2); alo[2] = f2tf32(a2 - __uint_as_float(ahi[2]));
            ahi[3] = f2tf32(a3); alo[3] = f2tf32(a3 - __uint_as_float(ahi[3]));

            #pragma unroll
            for (int nt = 0; nt < 8; nt++) {
                float b0 = Ks[(nt*8 + g) * QK_STRIDE + k0 + tg];
                float b1 = Ks[(nt*8 + g) * QK_STRIDE + k0 + tg + 4];
                u32 bhi[2], blo[2];
                bhi[0] = f2tf32(b0); blo[0] = f2tf32(b0 - __uint_as_float(bhi[0]));
                bhi[1] = f2tf32(b1); blo[1] = f2tf32(b1 - __uint_as_float(bhi[1]));
                mma_tf32(Sa[nt], ahi, bhi);
                mma_tf32(Sa[nt], ahi, blo);
                mma_tf32(Sa[nt], alo, bhi);
            }
        }

        // ---- scale + mask ----
        #pragma unroll
        for (int nt = 0; nt < 8; nt++) {
            #pragma unroll
            for (int cc = 0; cc < 2; cc++) {
                int gj = n0 + nt*8 + 2*tg + cc;
                bool v0 = (gj <= gi0) && (gj + WINDOW_SZ > gi0);
                bool v1 = (gj <= gi1) && (gj + WINDOW_SZ > gi1);
                Sa[nt][cc]     = v0 ? Sa[nt][cc]     * SCALE_ATTN : -1.0e30f;
                Sa[nt][2 + cc] = v1 ? Sa[nt][2 + cc] * SCALE_ATTN : -1.0e30f;
            }
        }

        // ---- online softmax (rows gi0, gi1; reduce over quad lanes) ----
        float tm0 = -1.0e30f, tm1 = -1.0e30f;
        #pragma unroll
        for (int nt = 0; nt < 8; nt++) {
            tm0 = fmaxf(tm0, fmaxf(Sa[nt][0], Sa[nt][1]));
            tm1 = fmaxf(tm1, fmaxf(Sa[nt][2], Sa[nt][3]));
        }
        tm0 = fmaxf(tm0, __shfl_xor_sync(0xffffffffu, tm0, 1));
        tm0 = fmaxf(tm0, __shfl_xor_sync(0xffffffffu, tm0, 2));
        tm1 = fmaxf(tm1, __shfl_xor_sync(0xffffffffu, tm1, 1));
        tm1 = fmaxf(tm1, __shfl_xor_sync(0xffffffffu, tm1, 2));

        float mn0 = fmaxf(m_r[0], tm0);
        float mn1 = fmaxf(m_r[1], tm1);
        float corr0 = __expf(m_r[0] - mn0);
        float corr1 = __expf(m_r[1] - mn1);
        m_r[0] = mn0; m_r[1] = mn1;

        float rs0 = 0.f, rs1 = 0.f;
        #pragma unroll
        for (int nt = 0; nt < 8; nt++) {
            #pragma unroll
            for (int cc = 0; cc < 2; cc++) {
                float p0 = __expf(Sa[nt][cc]     - mn0);
                float p1 = __expf(Sa[nt][2 + cc] - mn1);
                p0 = __uint_as_float(f2tf32(p0));   // round once, use for
                p1 = __uint_as_float(f2tf32(p1));   // both sum and PV mma
                Sa[nt][cc]     = p0;
                Sa[nt][2 + cc] = p1;
                rs0 += p0; rs1 += p1;
            }
        }
        rs0 += __shfl_xor_sync(0xffffffffu, rs0, 1);
        rs0 += __shfl_xor_sync(0xffffffffu, rs0, 2);
        rs1 += __shfl_xor_sync(0xffffffffu, rs1, 1);
        rs1 += __shfl_xor_sync(0xffffffffu, rs1, 2);

        l_r[0] = l_r[0] * corr0 + rs0;
        l_r[1] = l_r[1] * corr1 + rs1;
        #pragma unroll
        for (int nt = 0; nt < 8; nt++) {
            O[nt][0] *= corr0; O[nt][1] *= corr0;
            O[nt][2] *= corr1; O[nt][3] *= corr1;
        }

        // ---- store P (warp-private) ----
        #pragma unroll
        for (int nt = 0; nt < 8; nt++) {
            *(float2*)&Ps[g       * V_STRIDE + nt*8 + 2*tg] =
                make_float2(Sa[nt][0], Sa[nt][1]);
            *(float2*)&Ps[(g + 8) * V_STRIDE + nt*8 + 2*tg] =
                make_float2(Sa[nt][2], Sa[nt][3]);
        }
        __syncwarp();

        // ---- O += P V ----
        #pragma unroll
        for (int ks = 0; ks < 8; ks++) {
            int k0 = ks * 8;
            u32 pa[4];
            pa[0] = __float_as_uint(Ps[g       * V_STRIDE + k0 + tg]);
            pa[1] = __float_as_uint(Ps[(g + 8) * V_STRIDE + k0 + tg]);
            pa[2] = __float_as_uint(Ps[g       * V_STRIDE + k0 + tg + 4]);
            pa[3] = __float_as_uint(Ps[(g + 8) * V_STRIDE + k0 + tg + 4]);
            #pragma unroll
            for (int nt = 0; nt < 8; nt++) {
                u32 vb[2];
                vb[0] = __float_as_uint(Vs[(k0 + tg)     * V_STRIDE + nt*8 + g]);
                vb[1] = __float_as_uint(Vs[(k0 + tg + 4) * V_STRIDE + nt*8 + g]);
                mma_tf32(O[nt], pa, vb);
            }
        }
        __syncwarp();   // P reads done before next iteration overwrites
    }

    // ---- epilogue: out[t, h*64+vd] = O / l ----
    float inv0 = 1.0f / l_r[0];
    float inv1 = 1.0f / l_r[1];
    #pragma unroll
    for (int nt = 0; nt < 8; nt++) {
        int col = h * VDIM + nt*8 + 2*tg;
        *(float2*)(out + (size_t)gi0 * (NH * VDIM) + col) =
            make_float2(O[nt][0] * inv0, O[nt][1] * inv0);
        *(float2*)(out + (size_t)gi1 * (NH * VDIM) + col) =
            make_float2(O[nt][2] * inv1, O[nt][3] * inv1);
    }
}

// =====================================================================
// launch
// =====================================================================
extern "C" void kernel_launch(void* const* d_in, const int* in_sizes, int n_in,
                              void* d_out, int out_size)
{
    const int*   positions = (const int*)  d_in[0];
    const float* hidden    = (const float*)d_in[1];
    const float* Wqkv      = (const float*)d_in[2];
    const float* Wo        = (const float*)d_in[3];
    const float* sink      = (const float*)d_in[4];
    float* out = (float*)d_out;

    float *qkv, *attn;
    cudaGetSymbolAddress((void**)&qkv,  g_qkv);
    cudaGetSymbolAddress((void**)&attn, g_attn);

    cudaFuncSetAttribute(gemm_tf32_kernel,
                         cudaFuncAttributeMaxDynamicSharedMemorySize, GEMM_SMEM);
    cudaFuncSetAttribute(attn_kernel,
                         cudaFuncAttributeMaxDynamicSharedMemorySize, ATTN_SMEM);

    // 1) QKV projection (tf32 tensor cores)
    {
        dim3 grid(QKV_N / GBN, T_TOK / GBM);
        gemm_tf32_kernel<<<grid, 256, GEMM_SMEM>>>(hidden, Wqkv, qkv,
                                                   T_TOK, QKV_N, HID);
    }
    // 2) RoPE + V scale (in place)
    rope_kernel<<<T_TOK, 256>>>(qkv, positions);
    // 3) attention (tf32 tensor cores)
    {
        dim3 grid(T_TOK / A_BM, NH);
        attn_kernel<<<grid, 128, ATTN_SMEM>>>(qkv, sink, attn);
    }
    // 4) output projection (tf32 tensor cores)
    {
        dim3 grid(HID / GBN, T_TOK / GBM);
        gemm_tf32_kernel<<<grid, 256, GEMM_SMEM>>>(attn, Wo, out,
                                                   T_TOK, HID, NH * VDIM);
    }
}

// round 6
// speedup vs baseline: 3.4829x; 1.2122x over previous
#include <cuda_runtime.h>
#include <cuda_bf16.h>
#include <cstdint>
#include <math.h>

typedef unsigned int u32;

// ---------------- problem constants ----------------
#define T_TOK   2048
#define HID     4096
#define NH      32
#define NKH     8
#define HD      128
#define VDIM    64
#define QKV_N   (NH*HD + NKH*HD + NKH*VDIM)   // 5632
#define K_OFF   (NH*HD)                        // 4096
#define V_OFF   (NH*HD + NKH*HD)               // 5120
#define WINDOW_SZ 1024
#define SCALE_ATTN 0.08838834764831845f        // 128^-0.5
#define V_SCALE_C  1.25f

// ---------------- scratch (no allocs allowed) ----------------
__device__ float g_qkv [T_TOK * QKV_N];
__device__ float g_attn[T_TOK * NH * VDIM];

// =====================================================================
// mma helpers
// =====================================================================
__device__ __forceinline__ u32 f2tf32(float f) {
    u32 r;
    asm("cvt.rna.tf32.f32 %0, %1;" : "=r"(r) : "f"(f));
    return r;
}

__device__ __forceinline__ void mma_tf32(float c[4], const u32 a[4],
                                         const u32 b[2]) {
    asm volatile(
        "mma.sync.aligned.m16n8k8.row.col.f32.tf32.tf32.f32 "
        "{%0,%1,%2,%3}, {%4,%5,%6,%7}, {%8,%9}, {%0,%1,%2,%3};\n"
        : "+f"(c[0]), "+f"(c[1]), "+f"(c[2]), "+f"(c[3])
        : "r"(a[0]), "r"(a[1]), "r"(a[2]), "r"(a[3]), "r"(b[0]), "r"(b[1]));
}

__device__ __forceinline__ void mma_bf16(float c[4], const u32 a[4],
                                         const u32 b[2]) {
    asm volatile(
        "mma.sync.aligned.m16n8k16.row.col.f32.bf16.bf16.f32 "
        "{%0,%1,%2,%3}, {%4,%5,%6,%7}, {%8,%9}, {%0,%1,%2,%3};\n"
        : "+f"(c[0]), "+f"(c[1]), "+f"(c[2]), "+f"(c[3])
        : "r"(a[0]), "r"(a[1]), "r"(a[2]), "r"(a[3]), "r"(b[0]), "r"(b[1]));
}

// split two floats into packed bf16 hi-pair and lo-pair (truncation split:
// hi = top 16 bits of f; lo = bf16(f - hi); combined mantissa ~16 bits)
__device__ __forceinline__ void split2(float x, float y, u32& hi, u32& lo) {
    u32 bx = __float_as_uint(x), by = __float_as_uint(y);
    hi = __byte_perm(bx, by, 0x7632);
    float lx = x - __uint_as_float(bx & 0xffff0000u);
    float ly = y - __uint_as_float(by & 0xffff0000u);
    lo = __byte_perm(__float_as_uint(lx), __float_as_uint(ly), 0x7632);
}

// =====================================================================
// TF32 tensor-core GEMM (unchanged, known-good):
// C[M,N] = A[M,K] @ B[K,N], 128x128 tile, BK=32, 8 warps, m16n8k8.
// =====================================================================
#define GBM 128
#define GBN 128
#define GBK 32
#define AS_STRIDE 36
#define BS_STRIDE 132
#define AS_ELEMS (GBM*AS_STRIDE)
#define BS_ELEMS (GBK*BS_STRIDE)
#define GEMM_SMEM ((2*AS_ELEMS + 2*BS_ELEMS) * 4)

__global__ __launch_bounds__(256, 2) void gemm_tf32_kernel(
    const float* __restrict__ A, const float* __restrict__ B,
    float* __restrict__ C, int M, int N, int K)
{
    extern __shared__ u32 smem_u[];
    u32* As = smem_u;
    u32* Bs = smem_u + 2 * AS_ELEMS;

    const int tid  = threadIdx.x;
    const int warp = tid >> 5;
    const int lane = tid & 31;
    const int wr = warp >> 2;
    const int wc = warp & 3;
    const int g  = lane >> 2;
    const int tg = lane & 3;

    const int bx = blockIdx.x, by = blockIdx.y;
    const float* Ab = A + (size_t)by * GBM * K;
    const float* Bb = B + (size_t)bx * GBN;

    const int arow0 = tid >> 3;
    const int acol  = (tid & 7) * 4;
    const int brow0 = tid >> 5;
    const int bcol  = (tid & 31) * 4;

    float acc[4][4][4];
    #pragma unroll
    for (int i = 0; i < 4; i++)
        #pragma unroll
        for (int j = 0; j < 4; j++)
            #pragma unroll
            for (int r = 0; r < 4; r++) acc[i][j][r] = 0.f;

    const int nc = K / GBK;

    #pragma unroll
    for (int p = 0; p < 4; p++) {
        int r = arow0 + p * 32;
        float4 v = *(const float4*)(Ab + (size_t)r * K + acol);
        u32* d = &As[r * AS_STRIDE + acol];
        d[0] = f2tf32(v.x); d[1] = f2tf32(v.y); d[2] = f2tf32(v.z); d[3] = f2tf32(v.w);
    }
    #pragma unroll
    for (int p = 0; p < 4; p++) {
        int r = brow0 + p * 8;
        float4 v = *(const float4*)(Bb + (size_t)r * N + bcol);
        u32* d = &Bs[r * BS_STRIDE + bcol];
        d[0] = f2tf32(v.x); d[1] = f2tf32(v.y); d[2] = f2tf32(v.z); d[3] = f2tf32(v.w);
    }
    __syncthreads();

    int pb = 0;
    for (int c = 0; c < nc; c++) {
        float4 stA[4], stB[4];
        const bool has_next = (c + 1 < nc);
        if (has_next) {
            int k0 = (c + 1) * GBK;
            #pragma unroll
            for (int p = 0; p < 4; p++)
                stA[p] = *(const float4*)(Ab + (size_t)(arow0 + p*32) * K + k0 + acol);
            #pragma unroll
            for (int p = 0; p < 4; p++)
                stB[p] = *(const float4*)(Bb + (size_t)(k0 + brow0 + p*8) * N + bcol);
        }

        const u32* Ac = As + pb * AS_ELEMS;
        const u32* Bc = Bs + pb * BS_ELEMS;

        #pragma unroll
        for (int ks = 0; ks < 4; ks++) {
            u32 af[4][4], bf[4][2];
            #pragma unroll
            for (int mt = 0; mt < 4; mt++) {
                int base = (wr*64 + mt*16 + g) * AS_STRIDE + ks*8 + tg;
                af[mt][0] = Ac[base];
                af[mt][1] = Ac[base + 8*AS_STRIDE];
                af[mt][2] = Ac[base + 4];
                af[mt][3] = Ac[base + 8*AS_STRIDE + 4];
            }
            #pragma unroll
            for (int nt = 0; nt < 4; nt++) {
                int col = wc*32 + nt*8 + g;
                int idx = (ks*8 + tg) * BS_STRIDE + col;
                bf[nt][0] = Bc[idx];
                bf[nt][1] = Bc[idx + 4*BS_STRIDE];
            }
            #pragma unroll
            for (int mt = 0; mt < 4; mt++)
                #pragma unroll
                for (int nt = 0; nt < 4; nt++)
                    mma_tf32(acc[mt][nt], af[mt], bf[nt]);
        }

        if (has_next) {
            u32* An = As + (1 - pb) * AS_ELEMS;
            u32* Bn = Bs + (1 - pb) * BS_ELEMS;
            #pragma unroll
            for (int p = 0; p < 4; p++) {
                u32* d = &An[(arow0 + p*32) * AS_STRIDE + acol];
                d[0]=f2tf32(stA[p].x); d[1]=f2tf32(stA[p].y);
                d[2]=f2tf32(stA[p].z); d[3]=f2tf32(stA[p].w);
            }
            #pragma unroll
            for (int p = 0; p < 4; p++) {
                u32* d = &Bn[(brow0 + p*8) * BS_STRIDE + bcol];
                d[0]=f2tf32(stB[p].x); d[1]=f2tf32(stB[p].y);
                d[2]=f2tf32(stB[p].z); d[3]=f2tf32(stB[p].w);
            }
            __syncthreads();
            pb ^= 1;
        }
    }

    float* Cb = C + (size_t)by * GBM * N + (size_t)bx * GBN;
    #pragma unroll
    for (int mt = 0; mt < 4; mt++) {
        int row = wr*64 + mt*16 + g;
        #pragma unroll
        for (int nt = 0; nt < 4; nt++) {
            int col = wc*32 + nt*8 + tg*2;
            *(float2*)(Cb + (size_t)row * N + col) =
                make_float2(acc[mt][nt][0], acc[mt][nt][1]);
            *(float2*)(Cb + (size_t)(row + 8) * N + col) =
                make_float2(acc[mt][nt][2], acc[mt][nt][3]);
        }
    }
}

// =====================================================================
// RoPE + V scale (sincos computed once per token).
// =====================================================================
__global__ __launch_bounds__(256) void rope_kernel(
    float* __restrict__ qkv, const int* __restrict__ positions)
{
    __shared__ float cs[64], sn[64];
    const int t = blockIdx.x;
    const int tid = threadIdx.x;
    float* row = qkv + (size_t)t * QKV_N;

    if (tid < 64) {
        float pos = (float)positions[t];
        float inv = powf(1.0e6f, -(float)tid * (1.0f / 64.0f));
        float fr = pos * inv;
        float s, c;
        sincosf(fr, &s, &c);
        cs[tid] = c; sn[tid] = s;
    }
    __syncthreads();

    for (int idx = tid; idx < 40 * 64; idx += 256) {
        int head = idx >> 6;
        int i = idx & 63;
        int base = (head < NH) ? head * HD : K_OFF + (head - NH) * HD;
        float c = cs[i], s = sn[i];
        float x1 = row[base + i];
        float x2 = row[base + i + 64];
        row[base + i]      = x1 * c - x2 * s;
        row[base + i + 64] = x2 * c + x1 * s;
    }
    for (int idx = tid; idx < NKH * VDIM; idx += 256) {
        row[V_OFF + idx] *= V_SCALE_C;
    }
}

// =====================================================================
// Flash attention: S = QK^T via split-bf16 (hi/lo, 3x mma.m16n8k16),
// PV via tf32 (as before). Q fragments live in registers; K packed
// hi/lo bf16 pairs in smem (conversion once per tile at load).
// Block = (head, 64 q rows), 4 warps, warp = 16 q rows.
// =====================================================================
#define A_BM 64
#define KP_STRIDE 68           // u32 stride; (4g+tg) distinct banks
#define V_STRIDE  68
#define ATTN_SMEM ((2*64*KP_STRIDE + 64*V_STRIDE + 4*16*V_STRIDE) * 4)  // 68 KB

__global__ __launch_bounds__(128) void attn_kernel(
    const float* __restrict__ qkv, const float* __restrict__ sink,
    float* __restrict__ out)
{
    extern __shared__ u32 smem_a[];
    u32*   KPhi = smem_a;                         // [64][68] bf16x2 pairs (hi)
    u32*   KPlo = KPhi + 64 * KP_STRIDE;          // [64][68] (lo)
    float* Vs   = (float*)(KPlo + 64 * KP_STRIDE);// [64][68] tf32-rounded V
    float* Pw   = Vs + 64 * V_STRIDE;             // [4][16][68] warp-private P

    const int h  = blockIdx.y;
    const int m0 = blockIdx.x * A_BM;
    const int kh = h >> 2;

    const int tid  = threadIdx.x;
    const int warp = tid >> 5;
    const int lane = tid & 31;
    const int g  = lane >> 2;
    const int tg = lane & 3;
    const int wm = warp * 16;
    float* Ps = Pw + warp * 16 * V_STRIDE;

    const float* Kg = qkv + K_OFF + (size_t)kh * HD;
    const float* Vg = qkv + V_OFF + (size_t)kh * VDIM;

    // ---- Q fragments -> registers (split bf16 hi/lo), once per block ----
    u32 qhi[8][4], qlo[8][4];
    {
        const float* Qr0 = qkv + (size_t)(m0 + wm + g) * QKV_N + h * HD;
        const float* Qr1 = Qr0 + 8 * (size_t)QKV_N;
        #pragma unroll
        for (int ks = 0; ks < 8; ks++) {
            int c0 = ks * 16 + 2 * tg;
            float2 x0 = *(const float2*)(Qr0 + c0);
            float2 x1 = *(const float2*)(Qr1 + c0);
            float2 x2 = *(const float2*)(Qr0 + c0 + 8);
            float2 x3 = *(const float2*)(Qr1 + c0 + 8);
            split2(x0.x, x0.y, qhi[ks][0], qlo[ks][0]);
            split2(x1.x, x1.y, qhi[ks][1], qlo[ks][1]);
            split2(x2.x, x2.y, qhi[ks][2], qlo[ks][2]);
            split2(x3.x, x3.y, qhi[ks][3], qlo[ks][3]);
        }
    }

    const float snk = sink[h];
    float m_r[2] = {snk, snk};
    float l_r[2] = {1.0f, 1.0f};
    float O[8][4];
    #pragma unroll
    for (int nt = 0; nt < 8; nt++)
        #pragma unroll
        for (int r = 0; r < 4; r++) O[nt][r] = 0.f;

    const int gi0 = m0 + wm + g;
    const int gi1 = gi0 + 8;

    int n0s = m0 - WINDOW_SZ;
    if (n0s < 0) n0s = 0;

    for (int n0 = n0s; n0 <= m0; n0 += 64) {
        __syncthreads();   // previous K/V fully consumed

        // ---- load K tile, split to packed bf16 hi/lo pairs ----
        for (int idx = tid; idx < 64 * 32; idx += 128) {
            int r = idx >> 5, c4 = (idx & 31) * 4;
            float4 v = *(const float4*)(Kg + (size_t)(n0 + r) * QKV_N + c4);
            u32 h01, l01, h23, l23;
            split2(v.x, v.y, h01, l01);
            split2(v.z, v.w, h23, l23);
            int c2 = c4 >> 1;
            *(uint2*)&KPhi[r * KP_STRIDE + c2] = make_uint2(h01, h23);
            *(uint2*)&KPlo[r * KP_STRIDE + c2] = make_uint2(l01, l23);
        }
        // ---- load V tile (tf32-rounded) ----
        for (int idx = tid; idx < 64 * 16; idx += 128) {
            int r = idx >> 4, c4 = (idx & 15) * 4;
            float4 v = *(const float4*)(Vg + (size_t)(n0 + r) * QKV_N + c4);
            float* d = &Vs[r * V_STRIDE + c4];
            d[0] = __uint_as_float(f2tf32(v.x));
            d[1] = __uint_as_float(f2tf32(v.y));
            d[2] = __uint_as_float(f2tf32(v.z));
            d[3] = __uint_as_float(f2tf32(v.w));
        }
        __syncthreads();

        // ---- S = Q K^T (split bf16: hi*hi + lo*hi + hi*lo) ----
        float Sa[8][4];
        #pragma unroll
        for (int nt = 0; nt < 8; nt++)
            #pragma unroll
            for (int r = 0; r < 4; r++) Sa[nt][r] = 0.f;

        #pragma unroll
        for (int ks = 0; ks < 8; ks++) {
            #pragma unroll
            for (int nt = 0; nt < 8; nt++) {
                int base = (nt*8 + g) * KP_STRIDE + ks*8 + tg;
                u32 bh[2], bl[2];
                bh[0] = KPhi[base];     bh[1] = KPhi[base + 4];
                bl[0] = KPlo[base];     bl[1] = KPlo[base + 4];
                mma_bf16(Sa[nt], qhi[ks], bh);
                mma_bf16(Sa[nt], qlo[ks], bh);
                mma_bf16(Sa[nt], qhi[ks], bl);
            }
        }

        // ---- scale + mask ----
        #pragma unroll
        for (int nt = 0; nt < 8; nt++) {
            #pragma unroll
            for (int cc = 0; cc < 2; cc++) {
                int gj = n0 + nt*8 + 2*tg + cc;
                bool v0 = (gj <= gi0) && (gj + WINDOW_SZ > gi0);
                bool v1 = (gj <= gi1) && (gj + WINDOW_SZ > gi1);
                Sa[nt][cc]     = v0 ? Sa[nt][cc]     * SCALE_ATTN : -1.0e30f;
                Sa[nt][2 + cc] = v1 ? Sa[nt][2 + cc] * SCALE_ATTN : -1.0e30f;
            }
        }

        // ---- online softmax ----
        float tm0 = -1.0e30f, tm1 = -1.0e30f;
        #pragma unroll
        for (int nt = 0; nt < 8; nt++) {
            tm0 = fmaxf(tm0, fmaxf(Sa[nt][0], Sa[nt][1]));
            tm1 = fmaxf(tm1, fmaxf(Sa[nt][2], Sa[nt][3]));
        }
        tm0 = fmaxf(tm0, __shfl_xor_sync(0xffffffffu, tm0, 1));
        tm0 = fmaxf(tm0, __shfl_xor_sync(0xffffffffu, tm0, 2));
        tm1 = fmaxf(tm1, __shfl_xor_sync(0xffffffffu, tm1, 1));
        tm1 = fmaxf(tm1, __shfl_xor_sync(0xffffffffu, tm1, 2));

        float mn0 = fmaxf(m_r[0], tm0);
        float mn1 = fmaxf(m_r[1], tm1);
        float corr0 = __expf(m_r[0] - mn0);
        float corr1 = __expf(m_r[1] - mn1);
        m_r[0] = mn0; m_r[1] = mn1;

        float rs0 = 0.f, rs1 = 0.f;
        #pragma unroll
        for (int nt = 0; nt < 8; nt++) {
            #pragma unroll
            for (int cc = 0; cc < 2; cc++) {
                float p0 = __expf(Sa[nt][cc]     - mn0);
                float p1 = __expf(Sa[nt][2 + cc] - mn1);
                p0 = __uint_as_float(f2tf32(p0));
                p1 = __uint_as_float(f2tf32(p1));
                Sa[nt][cc]     = p0;
                Sa[nt][2 + cc] = p1;
                rs0 += p0; rs1 += p1;
            }
        }
        rs0 += __shfl_xor_sync(0xffffffffu, rs0, 1);
        rs0 += __shfl_xor_sync(0xffffffffu, rs0, 2);
        rs1 += __shfl_xor_sync(0xffffffffu, rs1, 1);
        rs1 += __shfl_xor_sync(0xffffffffu, rs1, 2);

        l_r[0] = l_r[0] * corr0 + rs0;
        l_r[1] = l_r[1] * corr1 + rs1;
        #pragma unroll
        for (int nt = 0; nt < 8; nt++) {
            O[nt][0] *= corr0; O[nt][1] *= corr0;
            O[nt][2] *= corr1; O[nt][3] *= corr1;
        }

        // ---- store P (warp-private) ----
        #pragma unroll
        for (int nt = 0; nt < 8; nt++) {
            *(float2*)&Ps[g       * V_STRIDE + nt*8 + 2*tg] =
                make_float2(Sa[nt][0], Sa[nt][1]);
            *(float2*)&Ps[(g + 8) * V_STRIDE + nt*8 + 2*tg] =
                make_float2(Sa[nt][2], Sa[nt][3]);
        }
        __syncwarp();

        // ---- O += P V (tf32) ----
        #pragma unroll
        for (int ks = 0; ks < 8; ks++) {
            int k0 = ks * 8;
            u32 pa[4];
            pa[0] = __float_as_uint(Ps[g       * V_STRIDE + k0 + tg]);
            pa[1] = __float_as_uint(Ps[(g + 8) * V_STRIDE + k0 + tg]);
            pa[2] = __float_as_uint(Ps[g       * V_STRIDE + k0 + tg + 4]);
            pa[3] = __float_as_uint(Ps[(g + 8) * V_STRIDE + k0 + tg + 4]);
            #pragma unroll
            for (int nt = 0; nt < 8; nt++) {
                u32 vb[2];
                vb[0] = __float_as_uint(Vs[(k0 + tg)     * V_STRIDE + nt*8 + g]);
                vb[1] = __float_as_uint(Vs[(k0 + tg + 4) * V_STRIDE + nt*8 + g]);
                mma_tf32(O[nt], pa, vb);
            }
        }
        __syncwarp();
    }

    // ---- epilogue ----
    float inv0 = 1.0f / l_r[0];
    float inv1 = 1.0f / l_r[1];
    #pragma unroll
    for (int nt = 0; nt < 8; nt++) {
        int col = h * VDIM + nt*8 + 2*tg;
        *(float2*)(out + (size_t)gi0 * (NH * VDIM) + col) =
            make_float2(O[nt][0] * inv0, O[nt][1] * inv0);
        *(float2*)(out + (size_t)gi1 * (NH * VDIM) + col) =
            make_float2(O[nt][2] * inv1, O[nt][3] * inv1);
    }
}

// =====================================================================
// launch
// =====================================================================
extern "C" void kernel_launch(void* const* d_in, const int* in_sizes, int n_in,
                              void* d_out, int out_size)
{
    const int*   positions = (const int*)  d_in[0];
    const float* hidden    = (const float*)d_in[1];
    const float* Wqkv      = (const float*)d_in[2];
    const float* Wo        = (const float*)d_in[3];
    const float* sink      = (const float*)d_in[4];
    float* out = (float*)d_out;

    float *qkv, *attn;
    cudaGetSymbolAddress((void**)&qkv,  g_qkv);
    cudaGetSymbolAddress((void**)&attn, g_attn);

    cudaFuncSetAttribute(gemm_tf32_kernel,
                         cudaFuncAttributeMaxDynamicSharedMemorySize, GEMM_SMEM);
    cudaFuncSetAttribute(attn_kernel,
                         cudaFuncAttributeMaxDynamicSharedMemorySize, ATTN_SMEM);

    // 1) QKV projection (tf32 tensor cores)
    {
        dim3 grid(QKV_N / GBN, T_TOK / GBM);
        gemm_tf32_kernel<<<grid, 256, GEMM_SMEM>>>(hidden, Wqkv, qkv,
                                                   T_TOK, QKV_N, HID);
    }
    // 2) RoPE + V scale
    rope_kernel<<<T_TOK, 256>>>(qkv, positions);
    // 3) attention (split-bf16 S, tf32 PV)
    {
        dim3 grid(T_TOK / A_BM, NH);
        attn_kernel<<<grid, 128, ATTN_SMEM>>>(qkv, sink, attn);
    }
    // 4) output projection (tf32 tensor cores)
    {
        dim3 grid(HID / GBN, T_TOK / GBM);
        gemm_tf32_kernel<<<grid, 256, GEMM_SMEM>>>(attn, Wo, out,
                                                   T_TOK, HID, NH * VDIM);
    }
}